// round 5
// baseline (speedup 1.0000x reference)
#include <cuda_runtime.h>
#include <cstdint>

#define CIN    64
#define COUT   64
#define KTAPS  9
#define TILE_M 128
#define CONV_THREADS 256
#define FS_STRIDE 68                         // floats per row (16B-aligned, 2-way-conflict pad)
#define GRID_CONV 296
#define W_FLOATS  (KTAPS*CIN*COUT)           // 36864 floats = 147456 B
#define FS_FLOATS (TILE_M*FS_STRIDE)         // 8704 floats  = 34816 B
#define SMEM_BYTES ((W_FLOATS + 2*FS_FLOATS)*4)   // 217088 B (< 227 KB opt-in)
#define LEAK 0.333f
#define BN_EPS 1e-4f

__device__ __align__(16) float g_psum[GRID_CONV*COUT];
__device__ __align__(16) float g_psq [GRID_CONV*COUT];
__device__ __align__(16) float g_scale[COUT];
__device__ __align__(16) float g_shift[COUT];

union F4U { float4 v; float f[4]; unsigned long long u[2]; };
union U2F { unsigned long long u; float f[2]; };

__device__ __forceinline__ unsigned long long pack2(float x) {
    unsigned long long r;
    asm("mov.b64 %0, {%1, %1};" : "=l"(r) : "f"(x));
    return r;
}
// Packed fp32x2 FMA (Blackwell): exact fp32 math, 2x per issue slot.
__device__ __forceinline__ void fma2(unsigned long long& d,
                                     unsigned long long a, unsigned long long b) {
    asm("fma.rn.f32x2 %0, %1, %2, %0;" : "+l"(d) : "l"(a), "l"(b));
}
__device__ __forceinline__ void cp16(unsigned saddr, const void* g) {
    asm volatile("cp.async.cg.shared.global [%0], [%1], 16;" :: "r"(saddr), "l"(g));
}
__device__ __forceinline__ void cp_commit() { asm volatile("cp.async.commit_group;"); }
__device__ __forceinline__ void cp_wait1()  { asm volatile("cp.async.wait_group 1;"); }
__device__ __forceinline__ void cp_wait0()  { asm volatile("cp.async.wait_group 0;"); }

__global__ void __launch_bounds__(CONV_THREADS, 1)
conv_kernel(const float* __restrict__ feats, const float* __restrict__ Wg,
            const int* __restrict__ nidx, const int* __restrict__ valid,
            float* __restrict__ out, int Nrows, int numTiles)
{
    extern __shared__ float smem[];
    float* Ws  = smem;
    float* Fs0 = smem + W_FLOATS;
    float* Fs1 = Fs0 + FS_FLOATS;

    const int tid = threadIdx.x;

    // Load all 9 weight tiles into smem once per (persistent) block.
    {
        const float4* src = (const float4*)Wg;
        float4*       dst = (float4*)Ws;
        #pragma unroll
        for (int i = 0; i < (W_FLOATS/4)/CONV_THREADS; i++)     // 36 iters exact
            dst[tid + i*CONV_THREADS] = src[tid + i*CONV_THREADS];
    }

    const int gr = tid >> 1;   // gather: row within tile (2 threads/row)
    const int gh = tid & 1;    // gather: which 32-float half
    const int tr = tid >> 3;   // compute: row group (0..31), 4 rows each
    const int tc = tid & 7;    // compute: col group (0..7), 8 cols each

    float ssum[8], ssq[8];
    #pragma unroll
    for (int j = 0; j < 8; j++) { ssum[j] = 0.f; ssq[j] = 0.f; }

    for (int tile = blockIdx.x; tile < numTiles; tile += gridDim.x) {
        const int base = tile * TILE_M;

        unsigned long long acc[4][4];
        #pragma unroll
        for (int r = 0; r < 4; r++)
            #pragma unroll
            for (int p = 0; p < 4; p++) acc[r][p] = 0ull;

        auto gather = [&](int k, float* fb) {
            float* dst = fb + gr*FS_STRIDE + gh*32;
            const int gn = base + gr;
            const float* src = nullptr;
            if (gn < Nrows) {
                const int off = gn*KTAPS + k;
                // 'valid' arrives 4 bytes/element (int32 0/1 or float32 0.0/1.0);
                // a nonzero-word test is correct for both encodings.
                if (valid[off] != 0) src = feats + (size_t)nidx[off]*CIN + gh*32;
            }
            if (src) {
                unsigned sa = (unsigned)__cvta_generic_to_shared(dst);
                #pragma unroll
                for (int j = 0; j < 8; j++) cp16(sa + j*16, src + j*4);
            } else {
                const float4 z = make_float4(0.f, 0.f, 0.f, 0.f);
                #pragma unroll
                for (int j = 0; j < 8; j++) ((float4*)dst)[j] = z;
            }
        };

        gather(0, Fs0);
        cp_commit();

        #pragma unroll 1
        for (int k = 0; k < KTAPS; k++) {
            float* cur = (k & 1) ? Fs1 : Fs0;
            if (k + 1 < KTAPS) {
                gather(k + 1, (k & 1) ? Fs0 : Fs1);   // safe: prior sync drained reads
                cp_commit();
                cp_wait1();                            // tap k complete (<=1 group pending)
            } else {
                cp_wait0();
            }
            __syncthreads();

            const float* f0p = cur + (tr*4 + 0)*FS_STRIDE;
            const float* f1p = cur + (tr*4 + 1)*FS_STRIDE;
            const float* f2p = cur + (tr*4 + 2)*FS_STRIDE;
            const float* f3p = cur + (tr*4 + 3)*FS_STRIDE;
            const float* wkp = Ws + k*CIN*COUT + tc*8;

            #pragma unroll 4
            for (int i = 0; i < CIN; i += 4) {
                F4U fa, fb2, fc, fd;
                fa.v  = *(const float4*)(f0p + i);
                fb2.v = *(const float4*)(f1p + i);
                fc.v  = *(const float4*)(f2p + i);
                fd.v  = *(const float4*)(f3p + i);
                #pragma unroll
                for (int s2 = 0; s2 < 4; s2++) {
                    F4U w0, w1;
                    w0.v = *(const float4*)(wkp + (i + s2)*COUT);
                    w1.v = *(const float4*)(wkp + (i + s2)*COUT + 4);
                    const unsigned long long pa = pack2(fa.f[s2]);
                    const unsigned long long pb = pack2(fb2.f[s2]);
                    const unsigned long long pc = pack2(fc.f[s2]);
                    const unsigned long long pd = pack2(fd.f[s2]);
                    fma2(acc[0][0], pa, w0.u[0]); fma2(acc[0][1], pa, w0.u[1]);
                    fma2(acc[0][2], pa, w1.u[0]); fma2(acc[0][3], pa, w1.u[1]);
                    fma2(acc[1][0], pb, w0.u[0]); fma2(acc[1][1], pb, w0.u[1]);
                    fma2(acc[1][2], pb, w1.u[0]); fma2(acc[1][3], pb, w1.u[1]);
                    fma2(acc[2][0], pc, w0.u[0]); fma2(acc[2][1], pc, w0.u[1]);
                    fma2(acc[2][2], pc, w1.u[0]); fma2(acc[2][3], pc, w1.u[1]);
                    fma2(acc[3][0], pd, w0.u[0]); fma2(acc[3][1], pd, w0.u[1]);
                    fma2(acc[3][2], pd, w1.u[0]); fma2(acc[3][3], pd, w1.u[1]);
                }
            }
            __syncthreads();
        }

        // Epilogue: store y tile + accumulate per-thread BN partial stats.
        #pragma unroll
        for (int r = 0; r < 4; r++) {
            const int gn = base + tr*4 + r;
            if (gn < Nrows) {
                U2F a0, a1, a2, a3;
                a0.u = acc[r][0]; a1.u = acc[r][1]; a2.u = acc[r][2]; a3.u = acc[r][3];
                const float4 o0 = make_float4(a0.f[0], a0.f[1], a1.f[0], a1.f[1]);
                const float4 o1 = make_float4(a2.f[0], a2.f[1], a3.f[0], a3.f[1]);
                float* op = out + (size_t)gn*COUT + tc*8;
                *(float4*)op       = o0;
                *(float4*)(op + 4) = o1;
                const float v[8] = {o0.x, o0.y, o0.z, o0.w, o1.x, o1.y, o1.z, o1.w};
                #pragma unroll
                for (int j = 0; j < 8; j++) { ssum[j] += v[j]; ssq[j] += v[j]*v[j]; }
            }
        }
    }

    // Deterministic block reduction of stats -> per-block partials.
    __syncthreads();
    float* red = Fs0;                       // reuse gather buffer (2048 floats needed)
    #pragma unroll
    for (int j = 0; j < 8; j++) red[tid*8 + j] = ssum[j];
    __syncthreads();
    if (tid < COUT) {
        const int sub = tid >> 3, j = tid & 7;
        float tot = 0.f;
        #pragma unroll 1
        for (int t = 0; t < 32; t++) tot += red[(t*8 + sub)*8 + j];
        g_psum[blockIdx.x*COUT + tid] = tot;
    }
    __syncthreads();
    #pragma unroll
    for (int j = 0; j < 8; j++) red[tid*8 + j] = ssq[j];
    __syncthreads();
    if (tid < COUT) {
        const int sub = tid >> 3, j = tid & 7;
        float tot = 0.f;
        #pragma unroll 1
        for (int t = 0; t < 32; t++) tot += red[(t*8 + sub)*8 + j];
        g_psq[blockIdx.x*COUT + tid] = tot;
    }
}

__global__ void stats_kernel(const float* __restrict__ gamma,
                             const float* __restrict__ beta, int Nrows)
{
    const int c = threadIdx.x;
    if (c >= COUT) return;
    double s = 0.0, q = 0.0;
    #pragma unroll 1
    for (int b = 0; b < GRID_CONV; b++) {
        s += (double)g_psum[b*COUT + c];
        q += (double)g_psq [b*COUT + c];
    }
    const float mean = (float)(s / (double)Nrows);
    const float var  = (float)(q / (double)Nrows) - mean*mean;
    const float sc   = rsqrtf(var + BN_EPS) * gamma[c];
    g_scale[c] = sc;
    g_shift[c] = beta[c] - mean * sc;
}

__global__ void bn_kernel(float* __restrict__ y, long long n4)
{
    const long long idx = (long long)blockIdx.x*blockDim.x + threadIdx.x;
    const int c = (int)((idx << 2) & 63);          // stride is multiple of 16 f4 -> fixed cols
    const float4 sc = *(const float4*)&g_scale[c];
    const float4 sh = *(const float4*)&g_shift[c];
    const long long stride = (long long)gridDim.x*blockDim.x;
    float4* p = (float4*)y;
    for (long long i = idx; i < n4; i += stride) {
        float4 v = p[i];
        float a = fmaf(v.x, sc.x, sh.x);
        float b = fmaf(v.y, sc.y, sh.y);
        float d = fmaf(v.z, sc.z, sh.z);
        float e = fmaf(v.w, sc.w, sh.w);
        v.x = (a >= 0.f) ? a : LEAK*a;
        v.y = (b >= 0.f) ? b : LEAK*b;
        v.z = (d >= 0.f) ? d : LEAK*d;
        v.w = (e >= 0.f) ? e : LEAK*e;
        p[i] = v;
    }
}

extern "C" void kernel_launch(void* const* d_in, const int* in_sizes, int n_in,
                              void* d_out, int out_size)
{
    const float* feats = (const float*)d_in[0];
    const float* Wg    = (const float*)d_in[1];
    const float* gamma = (const float*)d_in[2];
    const float* beta  = (const float*)d_in[3];
    const int*   nidx  = (const int*)d_in[4];
    const int*   valid = (const int*)d_in[5];
    float*       out   = (float*)d_out;

    const int Nrows    = in_sizes[0] / CIN;
    const int numTiles = (Nrows + TILE_M - 1) / TILE_M;

    cudaFuncSetAttribute(conv_kernel,
                         cudaFuncAttributeMaxDynamicSharedMemorySize, SMEM_BYTES);

    conv_kernel<<<GRID_CONV, CONV_THREADS, SMEM_BYTES>>>(
        feats, Wg, nidx, valid, out, Nrows, numTiles);
    stats_kernel<<<1, COUT>>>(gamma, beta, Nrows);
    const long long n4 = (long long)Nrows * COUT / 4;
    bn_kernel<<<2048, 256>>>(out, n4);
}

// round 8
// speedup vs baseline: 2.3182x; 2.3182x over previous
#include <cuda_runtime.h>
#include <cuda_bf16.h>
#include <cstdint>

#define CIN    64
#define COUT   64
#define KTAPS  9
#define TILE_M 128
#define MAXN   1048576
#define CONV_GRID 148
#define CONV_THREADS 128
#define SGRID  296
#define LEAK   0.333f
#define BN_EPS 1e-4f

// ---- smem layout (bytes) ----
#define SM_W        1024
#define W_BYTES     (KTAPS*16384)          // 147456: per-tap fragment block = 16KB
#define SM_A0       (SM_W + W_BYTES)       // 148480 (1024-aligned)
#define A_BYTES     32768                  // hi 16KB + lo 16KB (128 rows x 128B each)
#define SM_A1       (SM_A0 + A_BYTES)
#define SMEM_TOTAL  (SM_A1 + A_BYTES)      // 214016 < 227KB opt-in

// ---- device globals (static scratch; no runtime allocation) ----
__device__ __align__(256) __nv_bfloat16 g_feats2[(size_t)MAXN * 128]; // [row][hi0..63|lo0..63]
__device__ __align__(256) unsigned g_wfrag[KTAPS * 4096];             // lane-ordered B frags
__device__ __align__(16) float g_psum[SGRID*COUT];
__device__ __align__(16) float g_psq [SGRID*COUT];
__device__ __align__(16) float g_scale[COUT];
__device__ __align__(16) float g_shift[COUT];

// ---- PTX helpers (all legal on compute_103 virtual arch: sm_80-era ISA) ----
__device__ __forceinline__ unsigned smem_u32(const void* p) {
    unsigned a;
    asm("{ .reg .u64 t; cvta.to.shared.u64 t, %1; cvt.u32.u64 %0, t; }" : "=r"(a) : "l"(p));
    return a;
}
__device__ __forceinline__ void cp16(unsigned saddr, const void* g) {
    asm volatile("cp.async.cg.shared.global [%0], [%1], 16;" :: "r"(saddr), "l"(g));
}
__device__ __forceinline__ void cp_commit() { asm volatile("cp.async.commit_group;"); }
__device__ __forceinline__ void cp_wait1()  { asm volatile("cp.async.wait_group 1;"); }
__device__ __forceinline__ void cp_wait0()  { asm volatile("cp.async.wait_group 0;"); }

__device__ __forceinline__ void ldm4(unsigned* r, unsigned addr) {
    asm volatile("ldmatrix.sync.aligned.m8n8.x4.shared.b16 {%0,%1,%2,%3}, [%4];"
        : "=r"(r[0]), "=r"(r[1]), "=r"(r[2]), "=r"(r[3]) : "r"(addr));
}
__device__ __forceinline__ void lds128(unsigned* r, unsigned addr) {
    asm volatile("ld.shared.v4.u32 {%0,%1,%2,%3}, [%4];"
        : "=r"(r[0]), "=r"(r[1]), "=r"(r[2]), "=r"(r[3]) : "r"(addr));
}
__device__ __forceinline__ void mma16816(float* d, const unsigned* a,
                                         unsigned b0, unsigned b1) {
    asm volatile("mma.sync.aligned.m16n8k16.row.col.f32.bf16.bf16.f32 "
        "{%0,%1,%2,%3}, {%4,%5,%6,%7}, {%8,%9}, {%0,%1,%2,%3};"
        : "+f"(d[0]), "+f"(d[1]), "+f"(d[2]), "+f"(d[3])
        : "r"(a[0]), "r"(a[1]), "r"(a[2]), "r"(a[3]), "r"(b0), "r"(b1));
}
__device__ __forceinline__ unsigned sw128(unsigned byte) {
    return byte ^ ((byte >> 3) & 0x70);
}

// ---- preprocessing: fp32 feats -> (hi, lo) bf16 split, row layout [hi64|lo64] ----
__global__ void prep_feats(const float* __restrict__ f, int total2) {
    const int stride = gridDim.x * blockDim.x;
    for (int i = blockIdx.x * blockDim.x + threadIdx.x; i < total2; i += stride) {
        const float2 x = ((const float2*)f)[i];
        const __nv_bfloat16 h0 = __float2bfloat16(x.x);
        const __nv_bfloat16 h1 = __float2bfloat16(x.y);
        const __nv_bfloat16 l0 = __float2bfloat16(x.x - __bfloat162float(h0));
        const __nv_bfloat16 l1 = __float2bfloat16(x.y - __bfloat162float(h1));
        const int row = i >> 5, c2 = i & 31;         // 32 float2 per 64-elem row
        __nv_bfloat162* rp = (__nv_bfloat162*)(g_feats2 + (size_t)row * 128);
        __nv_bfloat162 hp; hp.x = h0; hp.y = h1;
        __nv_bfloat162 lp; lp.x = l0; lp.y = l1;
        rp[c2]      = hp;
        rp[32 + c2] = lp;
    }
}

// ---- weights -> mma.sync B fragments in exact per-lane order ----
// B frag for m16n8k16 (col): lane l, reg r: elements B[k0][n], B[k0+1][n]
//   with n = nt*8 + l/4, k0 = kt*16 + r*8 + (l%4)*2, B[k][n] = W[tap][ci=k][n].
// Stream order within (tap, kt): e = hilo*16 + nt*2 + r, grouped 4 per LDS.128.
// u32 index = ((tap*4 + kt)*8 + g)*128 + lane*4 + m, where e = g*4 + m.
__global__ void prep_w(const float* __restrict__ W) {
    const int stride = gridDim.x * blockDim.x;
    for (int i = blockIdx.x * blockDim.x + threadIdx.x; i < KTAPS * 4096; i += stride) {
        const int m    = i & 3;
        const int lane = (i >> 2) & 31;
        const int g    = (i >> 7) & 7;
        const int kt   = (i >> 10) & 3;
        const int tap  = i >> 12;
        const int e    = g * 4 + m;
        const int hilo = e >> 4;
        const int nt   = (e >> 1) & 7;
        const int r    = e & 1;
        const int n    = nt * 8 + (lane >> 2);
        const int k0   = kt * 16 + r * 8 + (lane & 3) * 2;
        const float x0 = W[tap * 4096 + k0 * 64 + n];
        const float x1 = W[tap * 4096 + (k0 + 1) * 64 + n];
        __nv_bfloat16 v0, v1;
        if (hilo == 0) {
            v0 = __float2bfloat16(x0);
            v1 = __float2bfloat16(x1);
        } else {
            const __nv_bfloat16 h0 = __float2bfloat16(x0);
            const __nv_bfloat16 h1 = __float2bfloat16(x1);
            v0 = __float2bfloat16(x0 - __bfloat162float(h0));
            v1 = __float2bfloat16(x1 - __bfloat162float(h1));
        }
        const unsigned u = ((unsigned)__bfloat16_as_ushort(v1) << 16) |
                            (unsigned)__bfloat16_as_ushort(v0);
        g_wfrag[i] = u;
    }
}

// ---- main conv: persistent, mma.sync bf16 split-precision ----
__global__ void __launch_bounds__(CONV_THREADS, 1)
conv_kernel(const int* __restrict__ nidx, const int* __restrict__ valid,
            float* __restrict__ out, int Nrows, int numTiles)
{
    extern __shared__ char smem[];
    const unsigned sbase = smem_u32(smem);
    const int tid = threadIdx.x, wid = tid >> 5, lane = tid & 31;

    {   // copy all 9 taps of pre-laned B fragments: 147456B
        const float4* src = (const float4*)g_wfrag;
        float4* dst = (float4*)(smem + SM_W);
        #pragma unroll
        for (int i = 0; i < (W_BYTES / 16) / CONV_THREADS; i++)   // 72 iters exact
            dst[tid + i * CONV_THREADS] = src[tid + i * CONV_THREADS];
    }
    __syncthreads();

    // ldmatrix per-lane row mapping: 4 matrices = (m0-7,k0-7),(m8-15,k0-7),
    // (m0-7,k8-15),(m8-15,k8-15); lanes 8j..8j+7 feed matrix j.
    int rowA[2];
    #pragma unroll
    for (int mt = 0; mt < 2; mt++)
        rowA[mt] = wid * 32 + mt * 16 + ((lane >> 3) & 1) * 8 + (lane & 7);
    const unsigned colh = ((unsigned)(lane >> 4)) * 16;  // k-halves 0 / +16B
    unsigned rbase[2], rxor[2];
    #pragma unroll
    for (int mt = 0; mt < 2; mt++) {
        rbase[mt] = (unsigned)rowA[mt] * 128;
        rxor[mt]  = ((unsigned)(rowA[mt] & 7)) << 4;
    }

    const unsigned dsw = sw128((unsigned)tid * 128) - (unsigned)tid * 128; // 0-based helper
    (void)dsw;

    for (int tile = blockIdx.x; tile < numTiles; tile += gridDim.x) {
        const int base = tile * TILE_M;

        float acc[2][8][4];
        #pragma unroll
        for (int mt = 0; mt < 2; mt++)
            #pragma unroll
            for (int nt = 0; nt < 8; nt++)
                #pragma unroll
                for (int c = 0; c < 4; c++) acc[mt][nt][c] = 0.f;

        auto gather = [&](int k, unsigned abuf) {
            const int gn = base + tid;
            const __nv_bfloat16* src = nullptr;
            if (gn < Nrows) {
                const int off = gn * KTAPS + k;
                if (valid[off] != 0) src = g_feats2 + (size_t)nidx[off] * 128;
            }
            const unsigned rb = (unsigned)tid * 128;
            const unsigned rx = ((unsigned)(tid & 7)) << 4;
            if (src) {
                #pragma unroll
                for (int j = 0; j < 8; j++) {
                    const unsigned o = rb + (((unsigned)j * 16) ^ rx);
                    cp16(sbase + abuf + o,         src + j * 8);       // hi
                    cp16(sbase + abuf + 16384 + o, src + 64 + j * 8);  // lo
                }
            } else {
                const float4 z = make_float4(0.f, 0.f, 0.f, 0.f);
                #pragma unroll
                for (int j = 0; j < 8; j++) {
                    const unsigned o = rb + (((unsigned)j * 16) ^ rx);
                    *(float4*)(smem + abuf + o)         = z;
                    *(float4*)(smem + abuf + 16384 + o) = z;
                }
            }
        };

        gather(0, SM_A0); cp_commit();
        gather(1, SM_A1); cp_commit();

        #pragma unroll 1
        for (int k = 0; k < KTAPS; k++) {
            const unsigned ab = (k & 1) ? SM_A1 : SM_A0;
            if (k < KTAPS - 1) cp_wait1(); else cp_wait0();
            __syncthreads();

            const unsigned hb = sbase + ab;
            const unsigned lb = hb + 16384;
            const unsigned wb = sbase + SM_W + (unsigned)k * 16384;

            #pragma unroll
            for (int kt = 0; kt < 4; kt++) {
                unsigned b[32];
                #pragma unroll
                for (int g = 0; g < 8; g++)
                    lds128(b + 4 * g, wb + (unsigned)(kt * 8 + g) * 512 + lane * 16);
                unsigned ah[2][4], al[2][4];
                #pragma unroll
                for (int mt = 0; mt < 2; mt++) {
                    const unsigned xk = ((unsigned)kt * 32 + colh) ^ rxor[mt];
                    ldm4(ah[mt], hb + rbase[mt] + xk);
                    ldm4(al[mt], lb + rbase[mt] + xk);
                }
                #pragma unroll
                for (int mt = 0; mt < 2; mt++)      // hi @ Whi
                    #pragma unroll
                    for (int nt = 0; nt < 8; nt++)
                        mma16816(acc[mt][nt], ah[mt], b[nt*2], b[nt*2+1]);
                #pragma unroll
                for (int mt = 0; mt < 2; mt++)      // hi @ Wlo
                    #pragma unroll
                    for (int nt = 0; nt < 8; nt++)
                        mma16816(acc[mt][nt], ah[mt], b[16+nt*2], b[16+nt*2+1]);
                #pragma unroll
                for (int mt = 0; mt < 2; mt++)      // lo @ Whi
                    #pragma unroll
                    for (int nt = 0; nt < 8; nt++)
                        mma16816(acc[mt][nt], al[mt], b[nt*2], b[nt*2+1]);
            }
            __syncthreads();                        // all reads done before refill
            if (k <= KTAPS - 3) { gather(k + 2, ab); cp_commit(); }
        }

        // epilogue: D frag (m16n8): c0,c1 @ (row, col..col+1); c2,c3 @ (row+8)
        const int r0 = lane >> 2, c0 = (lane & 3) * 2;
        #pragma unroll
        for (int mt = 0; mt < 2; mt++) {
            #pragma unroll
            for (int nt = 0; nt < 8; nt++) {
                const int grow = base + wid * 32 + mt * 16 + r0;
                const int col  = nt * 8 + c0;
                if (grow < Nrows) {
                    float2 v; v.x = acc[mt][nt][0]; v.y = acc[mt][nt][1];
                    *(float2*)(out + (size_t)grow * COUT + col) = v;
                }
                if (grow + 8 < Nrows) {
                    float2 v; v.x = acc[mt][nt][2]; v.y = acc[mt][nt][3];
                    *(float2*)(out + (size_t)(grow + 8) * COUT + col) = v;
                }
            }
        }
    }
}

// ---- BN stats: deterministic per-block partials ----
__global__ void stats_partial(const float* __restrict__ y, int Nrows)
{
    __shared__ float sm[256][8];
    const int tid = threadIdx.x;
    const int cg = tid & 15;    // float4 column group (0..15)
    const int sub = tid >> 4;   // row sub-lane (0..15)
    float4 s = make_float4(0, 0, 0, 0), q = make_float4(0, 0, 0, 0);
    const float4* p = (const float4*)y;
    for (long long r = (long long)blockIdx.x * 16 + sub; r < Nrows;
         r += (long long)gridDim.x * 16) {
        const float4 v = p[r * 16 + cg];
        s.x += v.x; s.y += v.y; s.z += v.z; s.w += v.w;
        q.x += v.x * v.x; q.y += v.y * v.y; q.z += v.z * v.z; q.w += v.w * v.w;
    }
    sm[tid][0] = s.x; sm[tid][1] = s.y; sm[tid][2] = s.z; sm[tid][3] = s.w;
    sm[tid][4] = q.x; sm[tid][5] = q.y; sm[tid][6] = q.z; sm[tid][7] = q.w;
    __syncthreads();
    if (tid < COUT) {
        const int c4 = tid >> 2, j = tid & 3;
        float ts = 0.f, tq = 0.f;
        #pragma unroll 1
        for (int u = 0; u < 16; u++) {
            ts += sm[u * 16 + c4][j];
            tq += sm[u * 16 + c4][4 + j];
        }
        g_psum[blockIdx.x * COUT + tid] = ts;
        g_psq [blockIdx.x * COUT + tid] = tq;
    }
}

__global__ void stats_finalize(const float* __restrict__ gamma,
                               const float* __restrict__ beta, int Nrows)
{
    const int c = threadIdx.x;
    if (c >= COUT) return;
    double s = 0.0, q = 0.0;
    #pragma unroll 1
    for (int b = 0; b < SGRID; b++) {
        s += (double)g_psum[b * COUT + c];
        q += (double)g_psq [b * COUT + c];
    }
    const float mean = (float)(s / (double)Nrows);
    const float var  = (float)(q / (double)Nrows) - mean * mean;
    const float sc   = rsqrtf(var + BN_EPS) * gamma[c];
    g_scale[c] = sc;
    g_shift[c] = beta[c] - mean * sc;
}

__global__ void bn_kernel(float* __restrict__ y, long long n4)
{
    const long long idx = (long long)blockIdx.x * blockDim.x + threadIdx.x;
    const int c = (int)((idx << 2) & 63);
    const float4 sc = *(const float4*)&g_scale[c];
    const float4 sh = *(const float4*)&g_shift[c];
    const long long stride = (long long)gridDim.x * blockDim.x;
    float4* p = (float4*)y;
    for (long long i = idx; i < n4; i += stride) {
        float4 v = p[i];
        const float a = fmaf(v.x, sc.x, sh.x);
        const float b = fmaf(v.y, sc.y, sh.y);
        const float d = fmaf(v.z, sc.z, sh.z);
        const float e = fmaf(v.w, sc.w, sh.w);
        v.x = (a >= 0.f) ? a : LEAK * a;
        v.y = (b >= 0.f) ? b : LEAK * b;
        v.z = (d >= 0.f) ? d : LEAK * d;
        v.w = (e >= 0.f) ? e : LEAK * e;
        p[i] = v;
    }
}

extern "C" void kernel_launch(void* const* d_in, const int* in_sizes, int n_in,
                              void* d_out, int out_size)
{
    const float* feats = (const float*)d_in[0];
    const float* Wg    = (const float*)d_in[1];
    const float* gamma = (const float*)d_in[2];
    const float* beta  = (const float*)d_in[3];
    const int*   nidx  = (const int*)d_in[4];
    const int*   valid = (const int*)d_in[5];
    float*       out   = (float*)d_out;

    const int Nrows    = in_sizes[0] / CIN;
    const int numTiles = (Nrows + TILE_M - 1) / TILE_M;

    cudaFuncSetAttribute(conv_kernel,
                         cudaFuncAttributeMaxDynamicSharedMemorySize, SMEM_TOTAL);

    prep_feats<<<2048, 256>>>(feats, Nrows * CIN / 2);
    prep_w<<<36, 1024>>>(Wg);
    conv_kernel<<<CONV_GRID, CONV_THREADS, SMEM_TOTAL>>>(nidx, valid, out, Nrows, numTiles);
    stats_partial<<<SGRID, 256>>>(out, Nrows);
    stats_finalize<<<1, COUT>>>(gamma, beta, Nrows);
    bn_kernel<<<2048, 256>>>(out, (long long)Nrows * COUT / 4);
}

// round 15
// speedup vs baseline: 2.4032x; 1.0367x over previous
#include <cuda_runtime.h>
#include <cuda_bf16.h>
#include <cstdint>

#define CIN    64
#define COUT   64
#define KTAPS  9
#define TILE_M 128
#define MAXN   1048576
#define CONV_GRID 148
#define CONV_THREADS 256
#define LEAK   0.333f
#define BN_EPS 1e-4f

// ---- smem layout (bytes) ----
#define SM_W        1024
#define W_BYTES     (KTAPS*16384)          // 147456: per-tap fragment block = 16KB
#define SM_A0       (SM_W + W_BYTES)       // 148480 (1024-aligned)
#define A_BYTES     32768                  // hi 16KB + lo 16KB (128 rows x 128B each)
#define SM_A1       (SM_A0 + A_BYTES)
#define SMEM_TOTAL  (SM_A1 + A_BYTES)      // 214016 < 227KB opt-in

// ---- device globals (static scratch; no runtime allocation) ----
__device__ __align__(256) __nv_bfloat16 g_feats2[(size_t)MAXN * 128]; // [row][hi0..63|lo0..63]
__device__ __align__(256) unsigned g_wfrag[KTAPS * 4096];             // lane-ordered B frags
__device__ __align__(16) float g_psum[CONV_GRID*COUT];
__device__ __align__(16) float g_psq [CONV_GRID*COUT];
__device__ __align__(16) float g_scale[COUT];
__device__ __align__(16) float g_shift[COUT];

// ---- PTX helpers (sm_80-era ISA, legal on compute_103 virtual arch) ----
__device__ __forceinline__ unsigned smem_u32(const void* p) {
    unsigned a;
    asm("{ .reg .u64 t; cvta.to.shared.u64 t, %1; cvt.u32.u64 %0, t; }" : "=r"(a) : "l"(p));
    return a;
}
__device__ __forceinline__ void cp16(unsigned saddr, const void* g) {
    asm volatile("cp.async.cg.shared.global [%0], [%1], 16;" :: "r"(saddr), "l"(g));
}
__device__ __forceinline__ void cp_commit() { asm volatile("cp.async.commit_group;"); }
__device__ __forceinline__ void cp_wait1()  { asm volatile("cp.async.wait_group 1;"); }

__device__ __forceinline__ void ldm4(unsigned* r, unsigned addr) {
    asm volatile("ldmatrix.sync.aligned.m8n8.x4.shared.b16 {%0,%1,%2,%3}, [%4];"
        : "=r"(r[0]), "=r"(r[1]), "=r"(r[2]), "=r"(r[3]) : "r"(addr));
}
__device__ __forceinline__ void lds128(unsigned* r, unsigned addr) {
    asm volatile("ld.shared.v4.u32 {%0,%1,%2,%3}, [%4];"
        : "=r"(r[0]), "=r"(r[1]), "=r"(r[2]), "=r"(r[3]) : "r"(addr));
}
__device__ __forceinline__ void mma16816(float* d, const unsigned* a,
                                         unsigned b0, unsigned b1) {
    asm volatile("mma.sync.aligned.m16n8k16.row.col.f32.bf16.bf16.f32 "
        "{%0,%1,%2,%3}, {%4,%5,%6,%7}, {%8,%9}, {%0,%1,%2,%3};"
        : "+f"(d[0]), "+f"(d[1]), "+f"(d[2]), "+f"(d[3])
        : "r"(a[0]), "r"(a[1]), "r"(a[2]), "r"(a[3]), "r"(b0), "r"(b1));
}

// ---- preprocessing: fp32 feats -> (hi, lo) bf16 split, row layout [hi64|lo64] ----
__global__ void prep_feats(const float* __restrict__ f, int total2) {
    const int stride = gridDim.x * blockDim.x;
    for (int i = blockIdx.x * blockDim.x + threadIdx.x; i < total2; i += stride) {
        const float2 x = ((const float2*)f)[i];
        const __nv_bfloat16 h0 = __float2bfloat16(x.x);
        const __nv_bfloat16 h1 = __float2bfloat16(x.y);
        const __nv_bfloat16 l0 = __float2bfloat16(x.x - __bfloat162float(h0));
        const __nv_bfloat16 l1 = __float2bfloat16(x.y - __bfloat162float(h1));
        const int row = i >> 5, c2 = i & 31;         // 32 float2 per 64-elem row
        __nv_bfloat162* rp = (__nv_bfloat162*)(g_feats2 + (size_t)row * 128);
        __nv_bfloat162 hp; hp.x = h0; hp.y = h1;
        __nv_bfloat162 lp; lp.x = l0; lp.y = l1;
        rp[c2]      = hp;
        rp[32 + c2] = lp;
    }
}

// ---- weights -> mma.sync B fragments in exact per-lane order ----
// B frag m16n8k16 (col): lane l, reg r: B[k0][n], B[k0+1][n],
//   n = nt*8 + l/4, k0 = kt*16 + r*8 + (l%4)*2, B[k][n] = W[tap][ci=k][n].
// Stream order within (tap, kt): e = hilo*16 + nt*2 + r, grouped 4 per LDS.128.
// u32 index = ((tap*4 + kt)*8 + g)*128 + lane*4 + m, where e = g*4 + m.
__global__ void prep_w(const float* __restrict__ W) {
    const int stride = gridDim.x * blockDim.x;
    for (int i = blockIdx.x * blockDim.x + threadIdx.x; i < KTAPS * 4096; i += stride) {
        const int m    = i & 3;
        const int lane = (i >> 2) & 31;
        const int g    = (i >> 7) & 7;
        const int kt   = (i >> 10) & 3;
        const int tap  = i >> 12;
        const int e    = g * 4 + m;
        const int hilo = e >> 4;
        const int nt   = (e >> 1) & 7;
        const int r    = e & 1;
        const int n    = nt * 8 + (lane >> 2);
        const int k0   = kt * 16 + r * 8 + (lane & 3) * 2;
        const float x0 = W[tap * 4096 + k0 * 64 + n];
        const float x1 = W[tap * 4096 + (k0 + 1) * 64 + n];
        __nv_bfloat16 v0, v1;
        if (hilo == 0) {
            v0 = __float2bfloat16(x0);
            v1 = __float2bfloat16(x1);
        } else {
            const __nv_bfloat16 h0 = __float2bfloat16(x0);
            const __nv_bfloat16 h1 = __float2bfloat16(x1);
            v0 = __float2bfloat16(x0 - __bfloat162float(h0));
            v1 = __float2bfloat16(x1 - __bfloat162float(h1));
        }
        g_wfrag[i] = ((unsigned)__bfloat16_as_ushort(v1) << 16) |
                      (unsigned)__bfloat16_as_ushort(v0);
    }
}

// ---- main conv: persistent, 8 warps, mma.sync bf16 split-precision,
//      cross-tile cp.async pipeline (parity by LOCAL tile iteration), fused stats ----
__global__ void __launch_bounds__(CONV_THREADS, 1)
conv_kernel(const int* __restrict__ nidx, const int* __restrict__ valid,
            float* __restrict__ out, int Nrows, int numTiles)
{
    extern __shared__ char smem[];
    const unsigned sbase = smem_u32(smem);
    const int tid = threadIdx.x, wid = tid >> 5, lane = tid & 31;
    const int mb = wid >> 1;        // m-block (0..3): rows mb*32..mb*32+31
    const int nh = wid & 1;         // n-half  (0..1): cols nh*32..nh*32+31

    {   // copy all 9 taps of pre-laned B fragments: 147456B
        const float4* src = (const float4*)g_wfrag;
        float4* dst = (float4*)(smem + SM_W);
        #pragma unroll
        for (int i = 0; i < (W_BYTES / 16) / CONV_THREADS; i++)   // 36 iters exact
            dst[tid + i * CONV_THREADS] = src[tid + i * CONV_THREADS];
    }
    __syncthreads();

    // ldmatrix per-lane A-row mapping (4 m8k8 matrices per x4)
    unsigned rbase[2], rxor[2];
    #pragma unroll
    for (int mt = 0; mt < 2; mt++) {
        const int rowA = mb * 32 + mt * 16 + ((lane >> 3) & 1) * 8 + (lane & 7);
        rbase[mt] = (unsigned)rowA * 128;
        rxor[mt]  = ((unsigned)(rowA & 7)) << 4;
    }
    const unsigned colh = ((unsigned)(lane >> 4)) * 16;   // k-half select

    // Gather: 2 threads per row; tid&1 selects hi/lo 128B half of the src row.
    const int grow_ = tid >> 1;
    const int ghalf = tid & 1;
    const unsigned g_rb = (unsigned)grow_ * 128 + (unsigned)ghalf * 16384;
    const unsigned g_rx = ((unsigned)(grow_ & 7)) << 4;

    auto gather = [&](int t, int k, unsigned abuf) {
        if (t >= numTiles) return;                     // empty group (commit outside)
        const int gn = t * TILE_M + grow_;
        const __nv_bfloat16* src = nullptr;
        if (gn < Nrows) {
            const int off = gn * KTAPS + k;
            if (valid[off] != 0)
                src = g_feats2 + (size_t)nidx[off] * 128 + ghalf * 64;
        }
        if (src) {
            #pragma unroll
            for (int j = 0; j < 8; j++)
                cp16(sbase + abuf + g_rb + (((unsigned)j * 16) ^ g_rx), src + j * 8);
        } else {
            const float4 z = make_float4(0.f, 0.f, 0.f, 0.f);
            #pragma unroll
            for (int j = 0; j < 8; j++)
                *(float4*)(smem + abuf + g_rb + (((unsigned)j * 16) ^ g_rx)) = z;
        }
    };
    // Buffer parity is a function of the block-LOCAL sequential tap index
    // (ti*9 + k); ti increments by 1 per processed tile, so parity (ti+k)&1
    // is continuous across tile boundaries (the global tile id strides by
    // gridDim.x = even, which broke this in R9).
    auto bufof = [&](int ti, int k) -> unsigned {
        return ((ti + k) & 1) ? SM_A1 : SM_A0;
    };

    float ssum[8], ssq[8];
    #pragma unroll
    for (int s = 0; s < 8; s++) { ssum[s] = 0.f; ssq[s] = 0.f; }

    const int r0 = lane >> 2, c0 = (lane & 3) * 2;

    // prime the 2-deep pipeline (ti = 0)
    if (blockIdx.x < numTiles) {
        gather(blockIdx.x, 0, bufof(0, 0)); cp_commit();
        gather(blockIdx.x, 1, bufof(0, 1)); cp_commit();
    }

    int ti = 0;
    for (int tile = blockIdx.x; tile < numTiles; tile += gridDim.x, ti++) {
        const int base = tile * TILE_M;

        float acc[2][4][4];
        #pragma unroll
        for (int mt = 0; mt < 2; mt++)
            #pragma unroll
            for (int nt = 0; nt < 4; nt++)
                #pragma unroll
                for (int c = 0; c < 4; c++) acc[mt][nt][c] = 0.f;

        #pragma unroll 1
        for (int k = 0; k < KTAPS; k++) {
            const unsigned ab = bufof(ti, k);
            cp_wait1();                 // tap k group complete (one group stays in flight)
            __syncthreads();

            const unsigned hb = sbase + ab;
            const unsigned lb = hb + 16384;
            const unsigned wb = sbase + SM_W + (unsigned)k * 16384;

            #pragma unroll
            for (int kt = 0; kt < 4; kt++) {
                unsigned bh[8], bl[8];
                {
                    const unsigned gbase = wb + (unsigned)(kt * 8) * 512 + lane * 16;
                    lds128(bh,     gbase + (unsigned)(nh * 2)     * 512);
                    lds128(bh + 4, gbase + (unsigned)(nh * 2 + 1) * 512);
                    lds128(bl,     gbase + (unsigned)(4 + nh * 2) * 512);
                    lds128(bl + 4, gbase + (unsigned)(5 + nh * 2) * 512);
                }
                unsigned ah[2][4], al[2][4];
                #pragma unroll
                for (int mt = 0; mt < 2; mt++) {
                    const unsigned xk = ((unsigned)kt * 32 + colh) ^ rxor[mt];
                    ldm4(ah[mt], hb + rbase[mt] + xk);
                    ldm4(al[mt], lb + rbase[mt] + xk);
                }
                #pragma unroll
                for (int mt = 0; mt < 2; mt++)          // hi @ Whi
                    #pragma unroll
                    for (int nt = 0; nt < 4; nt++)
                        mma16816(acc[mt][nt], ah[mt], bh[nt*2], bh[nt*2+1]);
                #pragma unroll
                for (int mt = 0; mt < 2; mt++)          // hi @ Wlo
                    #pragma unroll
                    for (int nt = 0; nt < 4; nt++)
                        mma16816(acc[mt][nt], ah[mt], bl[nt*2], bl[nt*2+1]);
                #pragma unroll
                for (int mt = 0; mt < 2; mt++)          // lo @ Whi
                    #pragma unroll
                    for (int nt = 0; nt < 4; nt++)
                        mma16816(acc[mt][nt], al[mt], bh[nt*2], bh[nt*2+1]);
            }
            __syncthreads();            // all reads done before refilling this buffer

            // refill this buffer with tap k+2 (crosses into next tile at k=7,8);
            // target ab == bufof(ti, k) == bufof(ti+1, (k+2)-9) by construction.
            int nt_ = tile, nk = k + 2;
            if (nk >= KTAPS) { nk -= KTAPS; nt_ += gridDim.x; }
            gather(nt_, nk, ab);
            cp_commit();
        }

        // epilogue: store + fused BN partial stats (registers only)
        #pragma unroll
        for (int mt = 0; mt < 2; mt++) {
            #pragma unroll
            for (int nt = 0; nt < 4; nt++) {
                const int grow = base + mb * 32 + mt * 16 + r0;
                const int col  = nh * 32 + nt * 8 + c0;
                if (grow < Nrows) {
                    float2 v; v.x = acc[mt][nt][0]; v.y = acc[mt][nt][1];
                    *(float2*)(out + (size_t)grow * COUT + col) = v;
                    ssum[nt*2]   += v.x; ssq[nt*2]   += v.x * v.x;
                    ssum[nt*2+1] += v.y; ssq[nt*2+1] += v.y * v.y;
                }
                if (grow + 8 < Nrows) {
                    float2 v; v.x = acc[mt][nt][2]; v.y = acc[mt][nt][3];
                    *(float2*)(out + (size_t)(grow + 8) * COUT + col) = v;
                    ssum[nt*2]   += v.x; ssq[nt*2]   += v.x * v.x;
                    ssum[nt*2+1] += v.y; ssq[nt*2+1] += v.y * v.y;
                }
            }
        }
    }

    // deterministic block reduction of BN partials
    __syncthreads();
    float* red = (float*)(smem + SM_A0);          // 256*16 floats = 16KB
    #pragma unroll
    for (int s = 0; s < 8; s++) {
        red[tid * 16 + s]     = ssum[s];
        red[tid * 16 + 8 + s] = ssq[s];
    }
    __syncthreads();
    if (tid < COUT) {
        const int c  = tid;
        const int ch = c >> 5;            // nh
        const int nt = (c >> 3) & 3;
        const int q  = (c & 7) >> 1;      // lane&3
        const int j  = c & 1;
        float ts = 0.f, tq = 0.f;
        #pragma unroll 1
        for (int wi = 0; wi < 4; wi++)
            #pragma unroll
            for (int li = 0; li < 8; li++) {
                const int t = (ch + wi * 2) * 32 + q + li * 4;
                ts += red[t * 16 + nt * 2 + j];
                tq += red[t * 16 + 8 + nt * 2 + j];
            }
        g_psum[blockIdx.x * COUT + c] = ts;
        g_psq [blockIdx.x * COUT + c] = tq;
    }
}

__global__ void stats_finalize(const float* __restrict__ gamma,
                               const float* __restrict__ beta, int Nrows)
{
    const int c = threadIdx.x;
    if (c >= COUT) return;
    double s = 0.0, q = 0.0;
    #pragma unroll 1
    for (int b = 0; b < CONV_GRID; b++) {
        s += (double)g_psum[b * COUT + c];
        q += (double)g_psq [b * COUT + c];
    }
    const float mean = (float)(s / (double)Nrows);
    const float var  = (float)(q / (double)Nrows) - mean * mean;
    const float sc   = rsqrtf(var + BN_EPS) * gamma[c];
    g_scale[c] = sc;
    g_shift[c] = beta[c] - mean * sc;
}

__global__ void bn_kernel(float* __restrict__ y, long long n4)
{
    const long long idx = (long long)blockIdx.x * blockDim.x + threadIdx.x;
    const int c = (int)((idx << 2) & 63);
    const float4 sc = *(const float4*)&g_scale[c];
    const float4 sh = *(const float4*)&g_shift[c];
    const long long stride = (long long)gridDim.x * blockDim.x;
    float4* p = (float4*)y;
    for (long long i = idx; i < n4; i += stride) {
        float4 v = p[i];
        const float a = fmaf(v.x, sc.x, sh.x);
        const float b = fmaf(v.y, sc.y, sh.y);
        const float d = fmaf(v.z, sc.z, sh.z);
        const float e = fmaf(v.w, sc.w, sh.w);
        v.x = (a >= 0.f) ? a : LEAK * a;
        v.y = (b >= 0.f) ? b : LEAK * b;
        v.z = (d >= 0.f) ? d : LEAK * d;
        v.w = (e >= 0.f) ? e : LEAK * e;
        p[i] = v;
    }
}

extern "C" void kernel_launch(void* const* d_in, const int* in_sizes, int n_in,
                              void* d_out, int out_size)
{
    const float* feats = (const float*)d_in[0];
    const float* Wg    = (const float*)d_in[1];
    const float* gamma = (const float*)d_in[2];
    const float* beta  = (const float*)d_in[3];
    const int*   nidx  = (const int*)d_in[4];
    const int*   valid = (const int*)d_in[5];
    float*       out   = (float*)d_out;

    const int Nrows    = in_sizes[0] / CIN;
    const int numTiles = (Nrows + TILE_M - 1) / TILE_M;

    cudaFuncSetAttribute(conv_kernel,
                         cudaFuncAttributeMaxDynamicSharedMemorySize, SMEM_TOTAL);

    prep_feats<<<2048, 256>>>(feats, Nrows * CIN / 2);
    prep_w<<<36, 1024>>>(Wg);
    conv_kernel<<<CONV_GRID, CONV_THREADS, SMEM_TOTAL>>>(nidx, valid, out, Nrows, numTiles);
    stats_finalize<<<1, COUT>>>(gamma, beta, Nrows);
    bn_kernel<<<2048, 256>>>(out, (long long)Nrows * COUT / 4);
}

// round 16
// speedup vs baseline: 2.5559x; 1.0635x over previous
#include <cuda_runtime.h>
#include <cuda_bf16.h>
#include <cstdint>

#define CIN    64
#define COUT   64
#define KTAPS  9
#define TILE_M 64
#define MAXN   1048576
#define CONV_GRID 148
#define CONV_THREADS 256
#define LEAK   0.333f
#define BN_EPS 1e-4f

// ---- smem layout (bytes) ----
#define SM_W        1024
#define W_BYTES     (KTAPS*16384)          // 147456: per-tap fragment block = 16KB
#define SM_A0       (SM_W + W_BYTES)       // 148480 (1024-aligned)
#define A_BYTES     16384                  // hi 8KB + lo 8KB (64 rows x 128B each)
#define NBUF        4
#define SMEM_TOTAL  (SM_A0 + NBUF*A_BYTES) // 214016 < 227KB opt-in

// ---- device globals (static scratch; no runtime allocation) ----
__device__ __align__(256) __nv_bfloat16 g_feats2[(size_t)MAXN * 128]; // [row][hi0..63|lo0..63]
__device__ __align__(256) unsigned g_wfrag[KTAPS * 4096];             // lane-ordered B frags
__device__ __align__(16) float g_psum[CONV_GRID*COUT];
__device__ __align__(16) float g_psq [CONV_GRID*COUT];
__device__ __align__(16) float g_scale[COUT];
__device__ __align__(16) float g_shift[COUT];

// ---- PTX helpers (sm_80-era ISA, legal on compute_103 virtual arch) ----
__device__ __forceinline__ unsigned smem_u32(const void* p) {
    unsigned a;
    asm("{ .reg .u64 t; cvta.to.shared.u64 t, %1; cvt.u32.u64 %0, t; }" : "=r"(a) : "l"(p));
    return a;
}
__device__ __forceinline__ void cp16(unsigned saddr, const void* g) {
    asm volatile("cp.async.cg.shared.global [%0], [%1], 16;" :: "r"(saddr), "l"(g));
}
__device__ __forceinline__ void cp_commit() { asm volatile("cp.async.commit_group;"); }
__device__ __forceinline__ void cp_wait2()  { asm volatile("cp.async.wait_group 2;"); }
__device__ __forceinline__ void cp_wait0()  { asm volatile("cp.async.wait_group 0;"); }

__device__ __forceinline__ void ldm4(unsigned* r, unsigned addr) {
    asm volatile("ldmatrix.sync.aligned.m8n8.x4.shared.b16 {%0,%1,%2,%3}, [%4];"
        : "=r"(r[0]), "=r"(r[1]), "=r"(r[2]), "=r"(r[3]) : "r"(addr));
}
__device__ __forceinline__ void lds128(unsigned* r, unsigned addr) {
    asm volatile("ld.shared.v4.u32 {%0,%1,%2,%3}, [%4];"
        : "=r"(r[0]), "=r"(r[1]), "=r"(r[2]), "=r"(r[3]) : "r"(addr));
}
__device__ __forceinline__ void mma16816(float* d, const unsigned* a,
                                         unsigned b0, unsigned b1) {
    asm volatile("mma.sync.aligned.m16n8k16.row.col.f32.bf16.bf16.f32 "
        "{%0,%1,%2,%3}, {%4,%5,%6,%7}, {%8,%9}, {%0,%1,%2,%3};"
        : "+f"(d[0]), "+f"(d[1]), "+f"(d[2]), "+f"(d[3])
        : "r"(a[0]), "r"(a[1]), "r"(a[2]), "r"(a[3]), "r"(b0), "r"(b1));
}

// ---- preprocessing: fp32 feats -> (hi, lo) bf16 split, row layout [hi64|lo64] ----
__global__ void prep_feats(const float* __restrict__ f, int total2) {
    const int stride = gridDim.x * blockDim.x;
    for (int i = blockIdx.x * blockDim.x + threadIdx.x; i < total2; i += stride) {
        const float2 x = ((const float2*)f)[i];
        const __nv_bfloat16 h0 = __float2bfloat16(x.x);
        const __nv_bfloat16 h1 = __float2bfloat16(x.y);
        const __nv_bfloat16 l0 = __float2bfloat16(x.x - __bfloat162float(h0));
        const __nv_bfloat16 l1 = __float2bfloat16(x.y - __bfloat162float(h1));
        const int row = i >> 5, c2 = i & 31;         // 32 float2 per 64-elem row
        __nv_bfloat162* rp = (__nv_bfloat162*)(g_feats2 + (size_t)row * 128);
        __nv_bfloat162 hp; hp.x = h0; hp.y = h1;
        __nv_bfloat162 lp; lp.x = l0; lp.y = l1;
        rp[c2]      = hp;
        rp[32 + c2] = lp;
    }
}

// ---- weights -> mma.sync B fragments in exact per-lane order (unchanged layout) ----
// B frag m16n8k16 (col): lane l, reg r: B[k0][n], B[k0+1][n],
//   n = nt*8 + l/4, k0 = kt*16 + r*8 + (l%4)*2, B[k][n] = W[tap][ci=k][n].
// Stream order within (tap, kt): e = hilo*16 + nt*2 + r, grouped 4 per LDS.128.
// u32 index = ((tap*4 + kt)*8 + g)*128 + lane*4 + m, where e = g*4 + m.
__global__ void prep_w(const float* __restrict__ W) {
    const int stride = gridDim.x * blockDim.x;
    for (int i = blockIdx.x * blockDim.x + threadIdx.x; i < KTAPS * 4096; i += stride) {
        const int m    = i & 3;
        const int lane = (i >> 2) & 31;
        const int g    = (i >> 7) & 7;
        const int kt   = (i >> 10) & 3;
        const int tap  = i >> 12;
        const int e    = g * 4 + m;
        const int hilo = e >> 4;
        const int nt   = (e >> 1) & 7;
        const int r    = e & 1;
        const int n    = nt * 8 + (lane >> 2);
        const int k0   = kt * 16 + r * 8 + (lane & 3) * 2;
        const float x0 = W[tap * 4096 + k0 * 64 + n];
        const float x1 = W[tap * 4096 + (k0 + 1) * 64 + n];
        __nv_bfloat16 v0, v1;
        if (hilo == 0) {
            v0 = __float2bfloat16(x0);
            v1 = __float2bfloat16(x1);
        } else {
            const __nv_bfloat16 h0 = __float2bfloat16(x0);
            const __nv_bfloat16 h1 = __float2bfloat16(x1);
            v0 = __float2bfloat16(x0 - __bfloat162float(h0));
            v1 = __float2bfloat16(x1 - __bfloat162float(h1));
        }
        g_wfrag[i] = ((unsigned)__bfloat16_as_ushort(v1) << 16) |
                      (unsigned)__bfloat16_as_ushort(v0);
    }
}

// ---- main conv: persistent, 8 warps (2 m-blocks x 4 n-quarters), TILE_M=64,
//      4-deep cross-tile cp.async pipeline, mma.sync bf16 split, fused stats ----
__global__ void __launch_bounds__(CONV_THREADS, 1)
conv_kernel(const int* __restrict__ nidx, const int* __restrict__ valid,
            float* __restrict__ out, int Nrows, int numTiles)
{
    extern __shared__ char smem[];
    const unsigned sbase = smem_u32(smem);
    const int tid = threadIdx.x, wid = tid >> 5, lane = tid & 31;
    const int mb = wid >> 2;        // m-block (0..1): rows mb*32..mb*32+31
    const int nq = wid & 3;         // n-quarter (0..3): cols nq*16..nq*16+15

    {   // copy all 9 taps of pre-laned B fragments: 147456B
        const float4* src = (const float4*)g_wfrag;
        float4* dst = (float4*)(smem + SM_W);
        #pragma unroll
        for (int i = 0; i < (W_BYTES / 16) / CONV_THREADS; i++)   // 36 iters exact
            dst[tid + i * CONV_THREADS] = src[tid + i * CONV_THREADS];
    }
    __syncthreads();

    // ldmatrix per-lane A-row mapping (4 m8k8 matrices per x4)
    unsigned rbase[2], rxor[2];
    #pragma unroll
    for (int mt = 0; mt < 2; mt++) {
        const int rowA = mb * 32 + mt * 16 + ((lane >> 3) & 1) * 8 + (lane & 7);
        rbase[mt] = (unsigned)rowA * 128;
        rxor[mt]  = ((unsigned)(rowA & 7)) << 4;
    }
    const unsigned colh = ((unsigned)(lane >> 4)) * 16;   // k-half select

    // Gather: 4 threads per row; quarter q: q<2 -> hi half, q>=2 -> lo half.
    const int grow_ = tid >> 2;           // 0..63
    const int ghilo = (tid >> 1) & 1;     // hi/lo tile
    const int gqq   = tid & 1;            // 64B sub-half within the 128B half
    const unsigned g_rb = (unsigned)grow_ * 128;
    const unsigned g_rx = ((unsigned)(grow_ & 7)) << 4;

    auto bufaddr = [&](int s) -> unsigned { return SM_A0 + (unsigned)(s & 3) * A_BYTES; };

    auto gather = [&](int t, int k, unsigned abuf) {
        if (t >= numTiles) return;                     // empty group (commit outside)
        const int gn = t * TILE_M + grow_;
        const __nv_bfloat16* src = nullptr;
        if (gn < Nrows) {
            const int off = gn * KTAPS + k;
            if (valid[off] != 0)
                src = g_feats2 + (size_t)nidx[off] * 128 + ghilo * 64 + gqq * 32;
        }
        const unsigned tb = abuf + (unsigned)ghilo * 8192;
        if (src) {
            #pragma unroll
            for (int j = 0; j < 4; j++)
                cp16(sbase + tb + g_rb + (((unsigned)(gqq * 64 + j * 16)) ^ g_rx),
                     src + j * 8);
        } else {
            const float4 z = make_float4(0.f, 0.f, 0.f, 0.f);
            #pragma unroll
            for (int j = 0; j < 4; j++)
                *(float4*)(smem + tb + g_rb + (((unsigned)(gqq * 64 + j * 16)) ^ g_rx)) = z;
        }
    };

    float ssum[4], ssq[4];
    #pragma unroll
    for (int s = 0; s < 4; s++) { ssum[s] = 0.f; ssq[s] = 0.f; }

    const int r0 = lane >> 2, c0 = (lane & 3) * 2;

    // prime the 4-deep pipeline: sequential tap indices 0,1,2 (taps 0..2 of first tile)
    {
        const int t0 = blockIdx.x;
        gather(t0, 0, bufaddr(0)); cp_commit();
        gather(t0, 1, bufaddr(1)); cp_commit();
        gather(t0, 2, bufaddr(2)); cp_commit();
    }

    int sq = 0;   // block-local sequential tap index (= ti*9 + k); buffer = sq & 3
    for (int tile = blockIdx.x; tile < numTiles; tile += gridDim.x) {
        const int base = tile * TILE_M;

        float acc[2][2][4];
        #pragma unroll
        for (int mt = 0; mt < 2; mt++)
            #pragma unroll
            for (int nt = 0; nt < 2; nt++)
                #pragma unroll
                for (int c = 0; c < 4; c++) acc[mt][nt][c] = 0.f;

        #pragma unroll 1
        for (int k = 0; k < KTAPS; k++, sq++) {
            const unsigned ab = bufaddr(sq);
            cp_wait2();                 // tap sq complete (sq+1, sq+2 still in flight)
            __syncthreads();

            const unsigned hb = sbase + ab;
            const unsigned lb = hb + 8192;
            const unsigned wb = sbase + SM_W + (unsigned)k * 16384;

            #pragma unroll
            for (int kt = 0; kt < 4; kt++) {
                unsigned bh[4], bl[4];
                const unsigned gbase = wb + (unsigned)(kt * 8) * 512 + lane * 16;
                lds128(bh, gbase + (unsigned)nq * 512);
                lds128(bl, gbase + (unsigned)(4 + nq) * 512);
                unsigned ah[2][4], al[2][4];
                #pragma unroll
                for (int mt = 0; mt < 2; mt++) {
                    const unsigned xk = ((unsigned)kt * 32 + colh) ^ rxor[mt];
                    ldm4(ah[mt], hb + rbase[mt] + xk);
                    ldm4(al[mt], lb + rbase[mt] + xk);
                }
                #pragma unroll
                for (int mt = 0; mt < 2; mt++)          // hi @ Whi
                    #pragma unroll
                    for (int nt = 0; nt < 2; nt++)
                        mma16816(acc[mt][nt], ah[mt], bh[nt*2], bh[nt*2+1]);
                #pragma unroll
                for (int mt = 0; mt < 2; mt++)          // hi @ Wlo
                    #pragma unroll
                    for (int nt = 0; nt < 2; nt++)
                        mma16816(acc[mt][nt], ah[mt], bl[nt*2], bl[nt*2+1]);
                #pragma unroll
                for (int mt = 0; mt < 2; mt++)          // lo @ Whi
                    #pragma unroll
                    for (int nt = 0; nt < 2; nt++)
                        mma16816(acc[mt][nt], al[mt], bh[nt*2], bh[nt*2+1]);
            }
            __syncthreads();            // all reads done before refilling this buffer

            // refill buffer (sq+3)&3 with tap sq+3 (crosses into the next tile);
            // its prior consumer was tap sq-1, whose MMA finished before this barrier.
            int nt_ = tile, nk = k + 3;
            if (nk >= KTAPS) { nk -= KTAPS; nt_ += gridDim.x; }
            gather(nt_, nk, bufaddr(sq + 3));
            cp_commit();
        }

        // epilogue: store + fused BN partial stats (registers only)
        #pragma unroll
        for (int mt = 0; mt < 2; mt++) {
            #pragma unroll
            for (int nt = 0; nt < 2; nt++) {
                const int grow = base + mb * 32 + mt * 16 + r0;
                const int col  = nq * 16 + nt * 8 + c0;
                if (grow < Nrows) {
                    float2 v; v.x = acc[mt][nt][0]; v.y = acc[mt][nt][1];
                    *(float2*)(out + (size_t)grow * COUT + col) = v;
                    ssum[nt*2]   += v.x; ssq[nt*2]   += v.x * v.x;
                    ssum[nt*2+1] += v.y; ssq[nt*2+1] += v.y * v.y;
                }
                if (grow + 8 < Nrows) {
                    float2 v; v.x = acc[mt][nt][2]; v.y = acc[mt][nt][3];
                    *(float2*)(out + (size_t)(grow + 8) * COUT + col) = v;
                    ssum[nt*2]   += v.x; ssq[nt*2]   += v.x * v.x;
                    ssum[nt*2+1] += v.y; ssq[nt*2+1] += v.y * v.y;
                }
            }
        }
    }

    // drain any pending (empty) cp.async groups before reusing A smem
    cp_wait0();
    __syncthreads();

    // deterministic block reduction of BN partials
    float* red = (float*)(smem + SM_A0);          // 256*8 floats = 8KB
    #pragma unroll
    for (int s = 0; s < 4; s++) {
        red[tid * 8 + s]     = ssum[s];
        red[tid * 8 + 4 + s] = ssq[s];
    }
    __syncthreads();
    if (tid < COUT) {
        const int c  = tid;
        const int cq = c >> 4;            // n-quarter
        const int s  = ((c >> 3) & 1) * 2 + (c & 1);
        const int q2 = (c >> 1) & 3;      // lane & 3
        float ts = 0.f, tq = 0.f;
        #pragma unroll
        for (int mbi = 0; mbi < 2; mbi++)
            #pragma unroll
            for (int l8 = 0; l8 < 8; l8++) {
                const int t = (mbi * 4 + cq) * 32 + l8 * 4 + q2;
                ts += red[t * 8 + s];
                tq += red[t * 8 + 4 + s];
            }
        g_psum[blockIdx.x * COUT + c] = ts;
        g_psq [blockIdx.x * COUT + c] = tq;
    }
}

// ---- parallel deterministic stats finalize: 16 chunks x 64 channels ----
__global__ void stats_finalize(const float* __restrict__ gamma,
                               const float* __restrict__ beta, int Nrows)
{
    __shared__ double sh_s[1024], sh_q[1024];
    const int t = threadIdx.x;
    const int c = t & 63, chunk = t >> 6;      // 16 chunks
    double s = 0.0, q = 0.0;
    for (int b = chunk; b < CONV_GRID; b += 16) {
        s += (double)g_psum[b * COUT + c];
        q += (double)g_psq [b * COUT + c];
    }
    sh_s[t] = s; sh_q[t] = q;
    __syncthreads();
    if (t < COUT) {
        double ts = 0.0, tq = 0.0;
        #pragma unroll
        for (int u = 0; u < 16; u++) { ts += sh_s[u * 64 + t]; tq += sh_q[u * 64 + t]; }
        const float mean = (float)(ts / (double)Nrows);
        const float var  = (float)(tq / (double)Nrows) - mean * mean;
        const float sc   = rsqrtf(var + BN_EPS) * gamma[t];
        g_scale[t] = sc;
        g_shift[t] = beta[t] - mean * sc;
    }
}

__global__ void bn_kernel(float* __restrict__ y, long long n4)
{
    const long long idx = (long long)blockIdx.x * blockDim.x + threadIdx.x;
    const int c = (int)((idx << 2) & 63);
    const float4 sc = *(const float4*)&g_scale[c];
    const float4 sh = *(const float4*)&g_shift[c];
    const long long stride = (long long)gridDim.x * blockDim.x;
    float4* p = (float4*)y;
    for (long long i = idx; i < n4; i += stride) {
        float4 v = p[i];
        const float a = fmaf(v.x, sc.x, sh.x);
        const float b = fmaf(v.y, sc.y, sh.y);
        const float d = fmaf(v.z, sc.z, sh.z);
        const float e = fmaf(v.w, sc.w, sh.w);
        v.x = (a >= 0.f) ? a : LEAK * a;
        v.y = (b >= 0.f) ? b : LEAK * b;
        v.z = (d >= 0.f) ? d : LEAK * d;
        v.w = (e >= 0.f) ? e : LEAK * e;
        p[i] = v;
    }
}

extern "C" void kernel_launch(void* const* d_in, const int* in_sizes, int n_in,
                              void* d_out, int out_size)
{
    const float* feats = (const float*)d_in[0];
    const float* Wg    = (const float*)d_in[1];
    const float* gamma = (const float*)d_in[2];
    const float* beta  = (const float*)d_in[3];
    const int*   nidx  = (const int*)d_in[4];
    const int*   valid = (const int*)d_in[5];
    float*       out   = (float*)d_out;

    const int Nrows    = in_sizes[0] / CIN;
    const int numTiles = (Nrows + TILE_M - 1) / TILE_M;

    cudaFuncSetAttribute(conv_kernel,
                         cudaFuncAttributeMaxDynamicSharedMemorySize, SMEM_TOTAL);

    prep_feats<<<2048, 256>>>(feats, Nrows * CIN / 2);
    prep_w<<<36, 1024>>>(Wg);
    conv_kernel<<<CONV_GRID, CONV_THREADS, SMEM_TOTAL>>>(nidx, valid, out, Nrows, numTiles);
    stats_finalize<<<1, 1024>>>(gamma, beta, Nrows);
    bn_kernel<<<2048, 256>>>(out, (long long)Nrows * COUT / 4);
}

// round 17
// speedup vs baseline: 4.7446x; 1.8563x over previous
#include <cuda_runtime.h>
#include <cuda_fp16.h>
#include <cstdint>

#define CIN    64
#define COUT   64
#define KTAPS  9
#define TILE_M 64
#define MAXN   1048576
#define CONV_GRID 296
#define CONV_THREADS 256
#define LEAK   0.333f
#define BN_EPS 1e-4f

// ---- smem layout (bytes) ----
#define SM_W        1024
#define W_TAP_BYTES 8192                   // per tap: 4 kt x 4 nq x 512B
#define W_BYTES     (KTAPS*W_TAP_BYTES)    // 73728
#define SM_A0       (SM_W + W_BYTES)       // 74752
#define A_BYTES     8192                   // 64 rows x 128B (fp16)
#define NBUF        4
#define SMEM_TOTAL  (SM_A0 + NBUF*A_BYTES) // 107520 -> 2 CTAs/SM (215040 < 227KB)

// ---- device globals (static scratch; no runtime allocation) ----
__device__ __align__(256) __half g_featsh[(size_t)MAXN * 64];   // [row][c] fp16
__device__ __align__(256) unsigned g_wfrag[KTAPS * 2048];       // lane-ordered B frags
__device__ __align__(16) float g_psum[CONV_GRID*COUT];
__device__ __align__(16) float g_psq [CONV_GRID*COUT];
__device__ __align__(16) float g_scale[COUT];
__device__ __align__(16) float g_shift[COUT];

// ---- PTX helpers (sm_80-era ISA, legal on compute_103 virtual arch) ----
__device__ __forceinline__ unsigned smem_u32(const void* p) {
    unsigned a;
    asm("{ .reg .u64 t; cvta.to.shared.u64 t, %1; cvt.u32.u64 %0, t; }" : "=r"(a) : "l"(p));
    return a;
}
__device__ __forceinline__ void cp16(unsigned saddr, const void* g) {
    asm volatile("cp.async.cg.shared.global [%0], [%1], 16;" :: "r"(saddr), "l"(g));
}
__device__ __forceinline__ void cp_commit() { asm volatile("cp.async.commit_group;"); }
__device__ __forceinline__ void cp_wait2()  { asm volatile("cp.async.wait_group 2;"); }
__device__ __forceinline__ void cp_wait0()  { asm volatile("cp.async.wait_group 0;"); }

__device__ __forceinline__ void ldm4(unsigned* r, unsigned addr) {
    asm volatile("ldmatrix.sync.aligned.m8n8.x4.shared.b16 {%0,%1,%2,%3}, [%4];"
        : "=r"(r[0]), "=r"(r[1]), "=r"(r[2]), "=r"(r[3]) : "r"(addr));
}
__device__ __forceinline__ void lds128(unsigned* r, unsigned addr) {
    asm volatile("ld.shared.v4.u32 {%0,%1,%2,%3}, [%4];"
        : "=r"(r[0]), "=r"(r[1]), "=r"(r[2]), "=r"(r[3]) : "r"(addr));
}
__device__ __forceinline__ void mma16816(float* d, const unsigned* a,
                                         unsigned b0, unsigned b1) {
    asm volatile("mma.sync.aligned.m16n8k16.row.col.f32.f16.f16.f32 "
        "{%0,%1,%2,%3}, {%4,%5,%6,%7}, {%8,%9}, {%0,%1,%2,%3};"
        : "+f"(d[0]), "+f"(d[1]), "+f"(d[2]), "+f"(d[3])
        : "r"(a[0]), "r"(a[1]), "r"(a[2]), "r"(a[3]), "r"(b0), "r"(b1));
}

// ---- preprocessing: fp32 feats -> fp16, row layout [64] (128B/row) ----
__global__ void prep_feats(const float* __restrict__ f, int total2) {
    const int stride = gridDim.x * blockDim.x;
    for (int i = blockIdx.x * blockDim.x + threadIdx.x; i < total2; i += stride) {
        const float2 x = ((const float2*)f)[i];
        const int row = i >> 5, c2 = i & 31;          // 32 float2 per 64-elem row
        __half2* rp = (__half2*)(g_featsh + (size_t)row * 64);
        rp[c2] = __floats2half2_rn(x.x, x.y);
    }
}

// ---- weights -> mma.sync B fragments (fp16) in exact per-lane order ----
// B frag m16n8k16 (col): lane l, reg r: B[k0][n], B[k0+1][n],
//   n = nq*16 + nt*8 + l/4, k0 = kt*16 + r*8 + (l%4)*2, B[k][n] = W[tap][ci=k][n].
// u32 index = ((tap*4 + kt)*4 + nq)*128 + lane*4 + (nt*2 + r)  -> one LDS.128
// per (tap, kt, nq) delivering the 4 b-regs for that warp's n-quarter.
__global__ void prep_w(const float* __restrict__ W) {
    const int stride = gridDim.x * blockDim.x;
    for (int i = blockIdx.x * blockDim.x + threadIdx.x; i < KTAPS * 2048; i += stride) {
        const int m    = i & 3;          // nt*2 + r
        const int lane = (i >> 2) & 31;
        const int nq   = (i >> 7) & 3;
        const int kt   = (i >> 9) & 3;
        const int tap  = i >> 11;
        const int nt   = m >> 1;
        const int r    = m & 1;
        const int n    = nq * 16 + nt * 8 + (lane >> 2);
        const int k0   = kt * 16 + r * 8 + (lane & 3) * 2;
        const __half v0 = __float2half_rn(W[tap * 4096 + k0 * 64 + n]);
        const __half v1 = __float2half_rn(W[tap * 4096 + (k0 + 1) * 64 + n]);
        g_wfrag[i] = ((unsigned)__half_as_ushort(v1) << 16) |
                      (unsigned)__half_as_ushort(v0);
    }
}

// ---- main conv: persistent, 2 CTAs/SM, 8 warps (2 m-blocks x 4 n-quarters),
//      TILE_M=64, 4-deep cross-tile cp.async pipeline, single fp16 GEMM,
//      fused deterministic BN partial stats ----
__global__ void __launch_bounds__(CONV_THREADS, 2)
conv_kernel(const int* __restrict__ nidx, const int* __restrict__ valid,
            float* __restrict__ out, int Nrows, int numTiles)
{
    extern __shared__ char smem[];
    const unsigned sbase = smem_u32(smem);
    const int tid = threadIdx.x, wid = tid >> 5, lane = tid & 31;
    const int mb = wid >> 2;        // m-block (0..1): rows mb*32..mb*32+31
    const int nq = wid & 3;         // n-quarter (0..3): cols nq*16..nq*16+15

    {   // copy all 9 taps of pre-laned B fragments: 73728B = 18 float4/thread
        const float4* src = (const float4*)g_wfrag;
        float4* dst = (float4*)(smem + SM_W);
        #pragma unroll
        for (int i = 0; i < (W_BYTES / 16) / CONV_THREADS; i++)
            dst[tid + i * CONV_THREADS] = src[tid + i * CONV_THREADS];
    }
    __syncthreads();

    // ldmatrix per-lane A-row mapping (4 m8k8 matrices per x4)
    unsigned rbase[2], rxor[2];
    #pragma unroll
    for (int mt = 0; mt < 2; mt++) {
        const int rowA = mb * 32 + mt * 16 + ((lane >> 3) & 1) * 8 + (lane & 7);
        rbase[mt] = (unsigned)rowA * 128;
        rxor[mt]  = ((unsigned)(rowA & 7)) << 4;
    }
    const unsigned colh = ((unsigned)(lane >> 4)) * 16;   // k-half select

    // Gather: 4 threads per row, each loads one 32B segment (2 cp16).
    const int grow_ = tid >> 2;           // 0..63
    const int gseg  = tid & 3;            // 32B segment
    const unsigned g_rb = (unsigned)grow_ * 128;
    const unsigned g_rx = ((unsigned)(grow_ & 7)) << 4;

    auto bufaddr = [&](int s) -> unsigned { return SM_A0 + (unsigned)(s & 3) * A_BYTES; };

    auto gather = [&](int t, int k, unsigned abuf) {
        if (t >= numTiles) return;                     // empty group (commit outside)
        const int gn = t * TILE_M + grow_;
        const __half* src = nullptr;
        if (gn < Nrows) {
            const int off = gn * KTAPS + k;
            if (valid[off] != 0)
                src = g_featsh + (size_t)nidx[off] * 64 + gseg * 16;
        }
        if (src) {
            #pragma unroll
            for (int j = 0; j < 2; j++)
                cp16(sbase + abuf + g_rb + (((unsigned)(gseg * 32 + j * 16)) ^ g_rx),
                     src + j * 8);
        } else {
            const float4 z = make_float4(0.f, 0.f, 0.f, 0.f);
            #pragma unroll
            for (int j = 0; j < 2; j++)
                *(float4*)(smem + abuf + g_rb + (((unsigned)(gseg * 32 + j * 16)) ^ g_rx)) = z;
        }
    };

    float ssum[4], ssq[4];
    #pragma unroll
    for (int s = 0; s < 4; s++) { ssum[s] = 0.f; ssq[s] = 0.f; }

    const int r0 = lane >> 2, c0 = (lane & 3) * 2;

    // prime the 4-deep pipeline: sequential tap indices 0,1,2 of the first tile
    {
        const int t0 = blockIdx.x;
        gather(t0, 0, bufaddr(0)); cp_commit();
        gather(t0, 1, bufaddr(1)); cp_commit();
        gather(t0, 2, bufaddr(2)); cp_commit();
    }

    int sq = 0;   // block-local sequential tap index (= ti*9 + k); buffer = sq & 3
    for (int tile = blockIdx.x; tile < numTiles; tile += gridDim.x) {
        const int base = tile * TILE_M;

        float acc[2][2][4];
        #pragma unroll
        for (int mt = 0; mt < 2; mt++)
            #pragma unroll
            for (int nt = 0; nt < 2; nt++)
                #pragma unroll
                for (int c = 0; c < 4; c++) acc[mt][nt][c] = 0.f;

        #pragma unroll 1
        for (int k = 0; k < KTAPS; k++, sq++) {
            const unsigned ab = bufaddr(sq);
            cp_wait2();                 // tap sq complete (sq+1, sq+2 still in flight)
            __syncthreads();

            const unsigned hb = sbase + ab;
            const unsigned wb = sbase + SM_W + (unsigned)k * W_TAP_BYTES;

            #pragma unroll
            for (int kt = 0; kt < 4; kt++) {
                unsigned bh[4];
                lds128(bh, wb + (unsigned)(kt * 4 + nq) * 512 + lane * 16);
                unsigned ah[2][4];
                #pragma unroll
                for (int mt = 0; mt < 2; mt++) {
                    const unsigned xk = ((unsigned)kt * 32 + colh) ^ rxor[mt];
                    ldm4(ah[mt], hb + rbase[mt] + xk);
                }
                #pragma unroll
                for (int mt = 0; mt < 2; mt++)
                    #pragma unroll
                    for (int nt = 0; nt < 2; nt++)
                        mma16816(acc[mt][nt], ah[mt], bh[nt*2], bh[nt*2+1]);
            }
            __syncthreads();            // all reads done before refilling this buffer

            // refill buffer (sq+3)&3 with tap sq+3 (crosses into the next tile);
            // its prior consumer was tap sq-1, whose MMA finished before this barrier.
            int nt_ = tile, nk = k + 3;
            if (nk >= KTAPS) { nk -= KTAPS; nt_ += gridDim.x; }
            gather(nt_, nk, bufaddr(sq + 3));
            cp_commit();
        }

        // epilogue: store + fused BN partial stats (registers only)
        #pragma unroll
        for (int mt = 0; mt < 2; mt++) {
            #pragma unroll
            for (int nt = 0; nt < 2; nt++) {
                const int grow = base + mb * 32 + mt * 16 + r0;
                const int col  = nq * 16 + nt * 8 + c0;
                if (grow < Nrows) {
                    float2 v; v.x = acc[mt][nt][0]; v.y = acc[mt][nt][1];
                    *(float2*)(out + (size_t)grow * COUT + col) = v;
                    ssum[nt*2]   += v.x; ssq[nt*2]   += v.x * v.x;
                    ssum[nt*2+1] += v.y; ssq[nt*2+1] += v.y * v.y;
                }
                if (grow + 8 < Nrows) {
                    float2 v; v.x = acc[mt][nt][2]; v.y = acc[mt][nt][3];
                    *(float2*)(out + (size_t)(grow + 8) * COUT + col) = v;
                    ssum[nt*2]   += v.x; ssq[nt*2]   += v.x * v.x;
                    ssum[nt*2+1] += v.y; ssq[nt*2+1] += v.y * v.y;
                }
            }
        }
    }

    // drain any pending (empty) cp.async groups before reusing A smem
    cp_wait0();
    __syncthreads();

    // deterministic block reduction of BN partials
    float* red = (float*)(smem + SM_A0);          // 256*8 floats = 8KB
    #pragma unroll
    for (int s = 0; s < 4; s++) {
        red[tid * 8 + s]     = ssum[s];
        red[tid * 8 + 4 + s] = ssq[s];
    }
    __syncthreads();
    if (tid < COUT) {
        const int c  = tid;
        const int cq = c >> 4;            // n-quarter
        const int s  = ((c >> 3) & 1) * 2 + (c & 1);
        const int q2 = (c >> 1) & 3;      // lane & 3
        float ts = 0.f, tq = 0.f;
        #pragma unroll
        for (int mbi = 0; mbi < 2; mbi++)
            #pragma unroll
            for (int l8 = 0; l8 < 8; l8++) {
                const int t = (mbi * 4 + cq) * 32 + l8 * 4 + q2;
                ts += red[t * 8 + s];
                tq += red[t * 8 + 4 + s];
            }
        g_psum[blockIdx.x * COUT + c] = ts;
        g_psq [blockIdx.x * COUT + c] = tq;
    }
}

// ---- parallel deterministic stats finalize: 16 chunks x 64 channels ----
__global__ void stats_finalize(const float* __restrict__ gamma,
                               const float* __restrict__ beta, int Nrows)
{
    __shared__ double sh_s[1024], sh_q[1024];
    const int t = threadIdx.x;
    const int c = t & 63, chunk = t >> 6;      // 16 chunks
    double s = 0.0, q = 0.0;
    for (int b = chunk; b < CONV_GRID; b += 16) {
        s += (double)g_psum[b * COUT + c];
        q += (double)g_psq [b * COUT + c];
    }
    sh_s[t] = s; sh_q[t] = q;
    __syncthreads();
    if (t < COUT) {
        double ts = 0.0, tq = 0.0;
        #pragma unroll
        for (int u = 0; u < 16; u++) { ts += sh_s[u * 64 + t]; tq += sh_q[u * 64 + t]; }
        const float mean = (float)(ts / (double)Nrows);
        const float var  = (float)(tq / (double)Nrows) - mean * mean;
        const float sc   = rsqrtf(var + BN_EPS) * gamma[t];
        g_scale[t] = sc;
        g_shift[t] = beta[t] - mean * sc;
    }
}

__global__ void bn_kernel(float* __restrict__ y, long long n4)
{
    const long long idx = (long long)blockIdx.x * blockDim.x + threadIdx.x;
    const int c = (int)((idx << 2) & 63);
    const float4 sc = *(const float4*)&g_scale[c];
    const float4 sh = *(const float4*)&g_shift[c];
    const long long stride = (long long)gridDim.x * blockDim.x;
    float4* p = (float4*)y;
    for (long long i = idx; i < n4; i += stride) {
        float4 v = p[i];
        const float a = fmaf(v.x, sc.x, sh.x);
        const float b = fmaf(v.y, sc.y, sh.y);
        const float d = fmaf(v.z, sc.z, sh.z);
        const float e = fmaf(v.w, sc.w, sh.w);
        v.x = (a >= 0.f) ? a : LEAK * a;
        v.y = (b >= 0.f) ? b : LEAK * b;
        v.z = (d >= 0.f) ? d : LEAK * d;
        v.w = (e >= 0.f) ? e : LEAK * e;
        p[i] = v;
    }
}

extern "C" void kernel_launch(void* const* d_in, const int* in_sizes, int n_in,
                              void* d_out, int out_size)
{
    const float* feats = (const float*)d_in[0];
    const float* Wg    = (const float*)d_in[1];
    const float* gamma = (const float*)d_in[2];
    const float* beta  = (const float*)d_in[3];
    const int*   nidx  = (const int*)d_in[4];
    const int*   valid = (const int*)d_in[5];
    float*       out   = (float*)d_out;

    const int Nrows    = in_sizes[0] / CIN;
    const int numTiles = (Nrows + TILE_M - 1) / TILE_M;

    cudaFuncSetAttribute(conv_kernel,
                         cudaFuncAttributeMaxDynamicSharedMemorySize, SMEM_TOTAL);

    prep_feats<<<2048, 256>>>(feats, Nrows * CIN / 2);
    prep_w<<<18, 1024>>>(Wg);
    conv_kernel<<<CONV_GRID, CONV_THREADS, SMEM_TOTAL>>>(nidx, valid, out, Nrows, numTiles);
    stats_finalize<<<1, 1024>>>(gamma, beta, Nrows);
    bn_kernel<<<2048, 256>>>(out, (long long)Nrows * COUT / 4);
}